// round 1
// baseline (speedup 1.0000x reference)
#include <cuda_runtime.h>
#include <cstdint>

#define NTOK 16384
#define DK   256
#define MC   1024
#define BV   32
#define COMMITC 0.25f
#define DECAYC  0.99f
#define EPSC    1e-5f
#define TEMPC   0.1f
#define LOGM    6.931471805599453f   /* ln(1024) */

// -------- static device scratch (no allocations allowed) --------
__device__ float g_S[2][NTOK][MC];       // dot-product scratch (reused both phases)
__device__ float g_xsq[2][NTOK];
__device__ float g_esq[MC];
__device__ int   g_idx[2][NTOK];         // [0]=a_idx, [1]=v_idx
__device__ float g_adj[2][NTOK];
__device__ float g_cnt[2][MC];           // [0]=c_v, [1]=c_a
__device__ float g_wsum[2][MC][DK];      // [0]=S_v, [1]=S_a
__device__ float g_ec[MC];
__device__ float g_en[MC][DK];
__device__ float g_loss;

// -------- packed f32x2 helpers (Blackwell FFMA2) --------
__device__ __forceinline__ unsigned long long ffma2(unsigned long long a,
                                                    unsigned long long b,
                                                    unsigned long long c) {
    unsigned long long d;
    asm("fma.rn.f32x2 %0, %1, %2, %3;" : "=l"(d) : "l"(a), "l"(b), "l"(c));
    return d;
}
__device__ __forceinline__ unsigned long long dup2(float x) {
    unsigned long long d;
    asm("mov.b64 %0, {%1, %1};" : "=l"(d) : "f"(x), "f"(x));
    return d;
}

// -------- zero accumulators (must run every launch for graph replay) --------
__global__ void k_zero() {
    unsigned i = blockIdx.x * blockDim.x + threadIdx.x;
    if (i < 2u * MC * DK) ((float*)g_wsum)[i] = 0.f;
    if (i < 2u * MC)      ((float*)g_cnt)[i]  = 0.f;
    if (i == 0)           g_loss = 0.f;
}

// -------- row squared norms: embedding rows then audio/video rows --------
__global__ void k_sq(const float* __restrict__ a, const float* __restrict__ v,
                     const float* __restrict__ e) {
    __shared__ float sb[256];
    int bid = blockIdx.x, t = threadIdx.x;
    const float* src; float* dst;
    if (bid < MC) { src = e + (size_t)bid * DK; dst = &g_esq[bid]; }
    else {
        int idx = bid - MC;
        int z = idx / NTOK, r = idx % NTOK;
        src = (z ? v : a) + (size_t)r * DK;
        dst = &g_xsq[z][r];
    }
    float x = src[t];
    sb[t] = x * x; __syncthreads();
    for (int o = 128; o > 0; o >>= 1) { if (t < o) sb[t] += sb[t + o]; __syncthreads(); }
    if (t == 0) *dst = sb[0];
}

// -------- NT GEMM: g_S[z] = X_z [NTOK,DK] @ Bm[MC,DK]^T --------
// 128x128x32 tile, 256 threads, 8x8 per thread via packed f32x2 FFMA.
__global__ void __launch_bounds__(256, 2)
k_gemm(const float* __restrict__ A0, const float* __restrict__ A1,
       const float* __restrict__ BmParam, int use_en) {
    __shared__ float As[32][128];
    __shared__ float Bs[32][128];
    const int z = blockIdx.z;
    const float* A  = z ? A1 : A0;
    const float* Bm = use_en ? &g_en[0][0] : BmParam;
    float* C = &g_S[0][0][0] + (size_t)z * NTOK * MC;
    const int bm = blockIdx.y * 128;
    const int bn = blockIdx.x * 128;
    const int t  = threadIdx.x;
    const int tx = t & 15, ty = t >> 4;
    const int lk = t & 7,  lr = t >> 3;   // lr in 0..31

    unsigned long long acc[8][4];
#pragma unroll
    for (int i = 0; i < 8; i++)
#pragma unroll
        for (int j = 0; j < 4; j++) acc[i][j] = 0ull;

    for (int k0 = 0; k0 < DK; k0 += 32) {
#pragma unroll
        for (int it = 0; it < 4; ++it) {
            int r = lr + 32 * it;
            float4 va = *(const float4*)(A  + (size_t)(bm + r) * DK + k0 + lk * 4);
            As[lk * 4 + 0][r] = va.x; As[lk * 4 + 1][r] = va.y;
            As[lk * 4 + 2][r] = va.z; As[lk * 4 + 3][r] = va.w;
            float4 vb = *(const float4*)(Bm + (size_t)(bn + r) * DK + k0 + lk * 4);
            Bs[lk * 4 + 0][r] = vb.x; Bs[lk * 4 + 1][r] = vb.y;
            Bs[lk * 4 + 2][r] = vb.z; Bs[lk * 4 + 3][r] = vb.w;
        }
        __syncthreads();
#pragma unroll
        for (int kk = 0; kk < 32; ++kk) {
            const float4 a0 = *(const float4*)&As[kk][ty * 8];
            const float4 a1 = *(const float4*)&As[kk][ty * 8 + 4];
            const ulonglong2 b0 = *(const ulonglong2*)&Bs[kk][tx * 8];
            const ulonglong2 b1 = *(const ulonglong2*)&Bs[kk][tx * 8 + 4];
            unsigned long long bb0 = b0.x, bb1 = b0.y, bb2 = b1.x, bb3 = b1.y;
            float av[8] = {a0.x, a0.y, a0.z, a0.w, a1.x, a1.y, a1.z, a1.w};
#pragma unroll
            for (int i = 0; i < 8; i++) {
                unsigned long long ad = dup2(av[i]);
                acc[i][0] = ffma2(ad, bb0, acc[i][0]);
                acc[i][1] = ffma2(ad, bb1, acc[i][1]);
                acc[i][2] = ffma2(ad, bb2, acc[i][2]);
                acc[i][3] = ffma2(ad, bb3, acc[i][3]);
            }
        }
        __syncthreads();
    }
#pragma unroll
    for (int i = 0; i < 8; i++) {
        size_t off = (size_t)(bm + ty * 8 + i) * MC + bn + tx * 8;
        *(ulonglong2*)(C + off)     = make_ulonglong2(acc[i][0], acc[i][1]);
        *(ulonglong2*)(C + off + 4) = make_ulonglong2(acc[i][2], acc[i][3]);
    }
}

// -------- phase-1 row pass: argmin(dist), entropy adjustment --------
__global__ void k_row1() {
    __shared__ float sred[256];
    __shared__ int   sidx[256];
    int row = blockIdx.x, z = blockIdx.y, t = threadIdx.x;
    const float* Srow = &g_S[z][row][0];
    float xs = g_xsq[z][row];

    float sv[4];
    float bestv = -1e30f; int besti = MC;
#pragma unroll
    for (int q = 0; q < 4; q++) {
        int m = q * 256 + t;
        float d = xs + g_esq[m] - 2.f * Srow[m];
        float s = -sqrtf(fmaxf(d, 0.f));
        sv[q] = s;
        if (s > bestv) { bestv = s; besti = m; }   // m ascending -> first-index kept
    }
    sred[t] = bestv; sidx[t] = besti; __syncthreads();
    for (int o = 128; o > 0; o >>= 1) {
        if (t < o) {
            float ov = sred[t + o]; int oi = sidx[t + o];
            if (ov > sred[t] || (ov == sred[t] && oi < sidx[t])) { sred[t] = ov; sidx[t] = oi; }
        }
        __syncthreads();
    }
    float rmax = sred[0]; int am = sidx[0]; __syncthreads();

    float eq[4], es = 0.f;
#pragma unroll
    for (int q = 0; q < 4; q++) { eq[q] = __expf(sv[q] - rmax); es += eq[q]; }
    sred[t] = es; __syncthreads();
    for (int o = 128; o > 0; o >>= 1) { if (t < o) sred[t] += sred[t + o]; __syncthreads(); }
    float invZ = 1.f / sred[0]; __syncthreads();

    float ent = 0.f;
#pragma unroll
    for (int q = 0; q < 4; q++) { float p = eq[q] * invZ; ent += p * __logf(p + 1e-5f); }
    sred[t] = ent; __syncthreads();
    for (int o = 128; o > 0; o >>= 1) { if (t < o) sred[t] += sred[t + o]; __syncthreads(); }
    if (t == 0) {
        float H = -sred[0];
        g_adj[z][row] = 1.f - H * (1.f / LOGM);
        g_idx[z][row] = am;
    }
}

// -------- EMA scatter: counts + weighted (a+v) sums --------
__global__ void k_scatter(const float* __restrict__ a, const float* __restrict__ v) {
    int row = blockIdx.x, t = threadIdx.x;
    int   ai = g_idx[0][row], vi = g_idx[1][row];
    float aadj = g_adj[0][row], vadj = g_adj[1][row];
    float tv = a[(size_t)row * DK + t] + v[(size_t)row * DK + t];
    atomicAdd(&g_wsum[0][vi][t], vadj * tv);   // video-driven pass
    atomicAdd(&g_wsum[1][ai][t], aadj * tv);   // audio-driven pass
    if (t == 0) {
        atomicAdd(&g_cnt[0][vi], vadj);
        atomicAdd(&g_cnt[1][ai], aadj);
    }
}

// -------- sequential EMA count normalization (1 block, M threads) --------
__global__ void k_ec(const float* __restrict__ ema_count) {
    __shared__ float sb[MC];
    int t = threadIdx.x;
    float ec = DECAYC * ema_count[t] + (1.f - DECAYC) * g_cnt[0][t];
    sb[t] = ec; __syncthreads();
    for (int o = 512; o > 0; o >>= 1) { if (t < o) sb[t] += sb[t + o]; __syncthreads(); }
    float n1 = sb[0]; __syncthreads();
    ec = (ec + EPSC) / (n1 + MC * EPSC) * n1;
    ec = DECAYC * ec + (1.f - DECAYC) * g_cnt[1][t];
    sb[t] = ec; __syncthreads();
    for (int o = 512; o > 0; o >>= 1) { if (t < o) sb[t] += sb[t + o]; __syncthreads(); }
    float n2 = sb[0]; __syncthreads();
    g_ec[t] = (ec + EPSC) / (n2 + MC * EPSC) * n2;
}

// -------- build normalized new codebook g_en --------
__global__ void k_en(const float* __restrict__ ema_weight) {
    __shared__ float sb[256];
    int m = blockIdx.x, t = threadIdx.x;
    float ew = (DECAYC * DECAYC) * ema_weight[(size_t)m * DK + t]
             + DECAYC * 0.5f * (1.f - DECAYC) * g_wsum[0][m][t]
             + 0.5f * (1.f - DECAYC) * g_wsum[1][m][t];
    float emb = ew / g_ec[m];
    sb[t] = emb * emb; __syncthreads();
    for (int o = 128; o > 0; o >>= 1) { if (t < o) sb[t] += sb[t + o]; __syncthreads(); }
    float nrm = sqrtf(sb[0]);
    g_en[m][t] = emb / fmaxf(nrm, 1e-8f);
}

// -------- phase-2 row pass: logsumexp + picked logits -> loss --------
__global__ void k_row2() {
    __shared__ float sred[256];
    __shared__ float spick[2];
    int row = blockIdx.x, z = blockIdx.y, t = threadIdx.x;
    const float* Srow = &g_S[z][row][0];
    float xs = g_xsq[z][row];
    float scale = 1.f / (fmaxf(sqrtf(xs), 1e-8f) * TEMPC);
    int self  = g_idx[z][row];
    int cross = g_idx[1 - z][row];

    float l[4], mx = -1e30f;
#pragma unroll
    for (int q = 0; q < 4; q++) {
        int m = q * 256 + t;
        l[q] = Srow[m] * scale;
        mx = fmaxf(mx, l[q]);
        if (m == self)  spick[0] = l[q];
        if (m == cross) spick[1] = l[q];
    }
    sred[t] = mx; __syncthreads();
    for (int o = 128; o > 0; o >>= 1) { if (t < o) sred[t] = fmaxf(sred[t], sred[t + o]); __syncthreads(); }
    float rmax = sred[0]; __syncthreads();
    float es = 0.f;
#pragma unroll
    for (int q = 0; q < 4; q++) es += __expf(l[q] - rmax);
    sred[t] = es; __syncthreads();
    for (int o = 128; o > 0; o >>= 1) { if (t < o) sred[t] += sred[t + o]; __syncthreads(); }
    if (t == 0) {
        float lse = __logf(sred[0]) + rmax;
        float contrib = lse - COMMITC * spick[0] - (1.f - COMMITC) * spick[1];
        atomicAdd(&g_loss, contrib);
    }
}

__global__ void k_final(float* __restrict__ out) {
    out[0] = COMMITC * g_loss / ((float)NTOK * (float)BV);
}

extern "C" void kernel_launch(void* const* d_in, const int* in_sizes, int n_in,
                              void* d_out, int out_size) {
    const float* audio      = (const float*)d_in[0];
    const float* video      = (const float*)d_in[1];
    const float* emb        = (const float*)d_in[2];
    const float* ema_count  = (const float*)d_in[3];
    const float* ema_weight = (const float*)d_in[4];
    float* out = (float*)d_out;

    k_zero<<<2048, 256>>>();
    k_sq<<<MC + 2 * NTOK, 256>>>(audio, video, emb);

    dim3 gg(MC / 128, NTOK / 128, 2);
    k_gemm<<<gg, 256>>>(audio, video, emb, 0);          // dist dots vs old codebook
    k_row1<<<dim3(NTOK, 2), 256>>>();
    k_scatter<<<NTOK, 256>>>(audio, video);
    k_ec<<<1, MC>>>(ema_count);
    k_en<<<MC, 256>>>(ema_weight);
    k_gemm<<<gg, 256>>>(audio, video, emb, 1);          // logits dots vs new codebook
    k_row2<<<dim3(NTOK, 2), 256>>>();
    k_final<<<1, 1>>>(out);
}

// round 2
// speedup vs baseline: 1.0037x; 1.0037x over previous
#include <cuda_runtime.h>
#include <cstdint>

#define NTOK 16384
#define DK   256
#define MC   1024
#define BV   32
#define COMMITC 0.25f
#define DECAYC  0.99f
#define EPSC    1e-5f
#define TEMPC   0.1f
#define LOGM    6.931471805599453f   /* ln(1024) */

// -------- static device scratch (no allocations allowed) --------
__device__ float g_S[2][NTOK][MC];       // dot-product scratch (reused both phases)
__device__ float g_xsq[2][NTOK];
__device__ float g_esq[MC];
__device__ int   g_idx[2][NTOK];         // [0]=a_idx, [1]=v_idx
__device__ float g_adj[2][NTOK];
__device__ float g_cnt[2][MC];           // [0]=c_v, [1]=c_a
__device__ float g_wsum[2][MC][DK];      // [0]=S_v, [1]=S_a
__device__ float g_ec[MC];
__device__ float g_en[MC][DK];
__device__ float g_loss;

// -------- packed f32x2 helpers (Blackwell FFMA2) --------
__device__ __forceinline__ unsigned long long ffma2(unsigned long long a,
                                                    unsigned long long b,
                                                    unsigned long long c) {
    unsigned long long d;
    asm("fma.rn.f32x2 %0, %1, %2, %3;" : "=l"(d) : "l"(a), "l"(b), "l"(c));
    return d;
}
__device__ __forceinline__ unsigned long long dup2(float x) {
    unsigned long long d;
    asm("mov.b64 %0, {%1, %1};" : "=l"(d) : "f"(x), "f"(x));
    return d;
}

// -------- zero accumulators (must run every launch for graph replay) --------
__global__ void k_zero() {
    unsigned i = blockIdx.x * blockDim.x + threadIdx.x;
    if (i < 2u * MC * DK) ((float*)g_wsum)[i] = 0.f;
    if (i < 2u * MC)      ((float*)g_cnt)[i]  = 0.f;
    if (i == 0)           g_loss = 0.f;
}

// -------- row squared norms: embedding rows then audio/video rows --------
__global__ void k_sq(const float* __restrict__ a, const float* __restrict__ v,
                     const float* __restrict__ e) {
    __shared__ float sb[256];
    int bid = blockIdx.x, t = threadIdx.x;
    const float* src; float* dst;
    if (bid < MC) { src = e + (size_t)bid * DK; dst = &g_esq[bid]; }
    else {
        int idx = bid - MC;
        int z = idx / NTOK, r = idx % NTOK;
        src = (z ? v : a) + (size_t)r * DK;
        dst = &g_xsq[z][r];
    }
    float x = src[t];
    sb[t] = x * x; __syncthreads();
    for (int o = 128; o > 0; o >>= 1) { if (t < o) sb[t] += sb[t + o]; __syncthreads(); }
    if (t == 0) *dst = sb[0];
}

// -------- NT GEMM: g_S[z] = X_z [NTOK,DK] @ Bm[MC,DK]^T --------
// 128x128x32 tile, 256 threads, 8x8 per thread via packed f32x2 FFMA.
__global__ void __launch_bounds__(256, 2)
k_gemm(const float* __restrict__ A0, const float* __restrict__ A1,
       const float* __restrict__ BmParam, int use_en) {
    __shared__ float As[32][128];
    __shared__ float Bs[32][128];
    const int z = blockIdx.z;
    const float* A  = z ? A1 : A0;
    const float* Bm = use_en ? &g_en[0][0] : BmParam;
    float* C = &g_S[0][0][0] + (size_t)z * NTOK * MC;
    const int bm = blockIdx.y * 128;
    const int bn = blockIdx.x * 128;
    const int t  = threadIdx.x;
    const int tx = t & 15, ty = t >> 4;
    const int lk = t & 7,  lr = t >> 3;   // lr in 0..31

    unsigned long long acc[8][4];
#pragma unroll
    for (int i = 0; i < 8; i++)
#pragma unroll
        for (int j = 0; j < 4; j++) acc[i][j] = 0ull;

    for (int k0 = 0; k0 < DK; k0 += 32) {
#pragma unroll
        for (int it = 0; it < 4; ++it) {
            int r = lr + 32 * it;
            float4 va = *(const float4*)(A  + (size_t)(bm + r) * DK + k0 + lk * 4);
            As[lk * 4 + 0][r] = va.x; As[lk * 4 + 1][r] = va.y;
            As[lk * 4 + 2][r] = va.z; As[lk * 4 + 3][r] = va.w;
            float4 vb = *(const float4*)(Bm + (size_t)(bn + r) * DK + k0 + lk * 4);
            Bs[lk * 4 + 0][r] = vb.x; Bs[lk * 4 + 1][r] = vb.y;
            Bs[lk * 4 + 2][r] = vb.z; Bs[lk * 4 + 3][r] = vb.w;
        }
        __syncthreads();
#pragma unroll
        for (int kk = 0; kk < 32; ++kk) {
            const float4 a0 = *(const float4*)&As[kk][ty * 8];
            const float4 a1 = *(const float4*)&As[kk][ty * 8 + 4];
            const ulonglong2 b0 = *(const ulonglong2*)&Bs[kk][tx * 8];
            const ulonglong2 b1 = *(const ulonglong2*)&Bs[kk][tx * 8 + 4];
            unsigned long long bb0 = b0.x, bb1 = b0.y, bb2 = b1.x, bb3 = b1.y;
            float av[8] = {a0.x, a0.y, a0.z, a0.w, a1.x, a1.y, a1.z, a1.w};
#pragma unroll
            for (int i = 0; i < 8; i++) {
                unsigned long long ad = dup2(av[i]);
                acc[i][0] = ffma2(ad, bb0, acc[i][0]);
                acc[i][1] = ffma2(ad, bb1, acc[i][1]);
                acc[i][2] = ffma2(ad, bb2, acc[i][2]);
                acc[i][3] = ffma2(ad, bb3, acc[i][3]);
            }
        }
        __syncthreads();
    }
#pragma unroll
    for (int i = 0; i < 8; i++) {
        size_t off = (size_t)(bm + ty * 8 + i) * MC + bn + tx * 8;
        *(ulonglong2*)(C + off)     = make_ulonglong2(acc[i][0], acc[i][1]);
        *(ulonglong2*)(C + off + 4) = make_ulonglong2(acc[i][2], acc[i][3]);
    }
}

// -------- phase-1 row pass: argmin(dist), entropy adjustment --------
__global__ void k_row1() {
    __shared__ float sred[256];
    __shared__ int   sidx[256];
    int row = blockIdx.x, z = blockIdx.y, t = threadIdx.x;
    const float* Srow = &g_S[z][row][0];
    float xs = g_xsq[z][row];

    float sv[4];
    float bestv = -1e30f; int besti = MC;
#pragma unroll
    for (int q = 0; q < 4; q++) {
        int m = q * 256 + t;
        float d = xs + g_esq[m] - 2.f * Srow[m];
        float s = -sqrtf(fmaxf(d, 0.f));
        sv[q] = s;
        if (s > bestv) { bestv = s; besti = m; }   // m ascending -> first-index kept
    }
    sred[t] = bestv; sidx[t] = besti; __syncthreads();
    for (int o = 128; o > 0; o >>= 1) {
        if (t < o) {
            float ov = sred[t + o]; int oi = sidx[t + o];
            if (ov > sred[t] || (ov == sred[t] && oi < sidx[t])) { sred[t] = ov; sidx[t] = oi; }
        }
        __syncthreads();
    }
    float rmax = sred[0]; int am = sidx[0]; __syncthreads();

    float eq[4], es = 0.f;
#pragma unroll
    for (int q = 0; q < 4; q++) { eq[q] = __expf(sv[q] - rmax); es += eq[q]; }
    sred[t] = es; __syncthreads();
    for (int o = 128; o > 0; o >>= 1) { if (t < o) sred[t] += sred[t + o]; __syncthreads(); }
    float invZ = 1.f / sred[0]; __syncthreads();

    float ent = 0.f;
#pragma unroll
    for (int q = 0; q < 4; q++) { float p = eq[q] * invZ; ent += p * __logf(p + 1e-5f); }
    sred[t] = ent; __syncthreads();
    for (int o = 128; o > 0; o >>= 1) { if (t < o) sred[t] += sred[t + o]; __syncthreads(); }
    if (t == 0) {
        float H = -sred[0];
        g_adj[z][row] = 1.f - H * (1.f / LOGM);
        g_idx[z][row] = am;
    }
}

// -------- EMA scatter: counts + weighted (a+v) sums --------
__global__ void k_scatter(const float* __restrict__ a, const float* __restrict__ v) {
    int row = blockIdx.x, t = threadIdx.x;
    int   ai = g_idx[0][row], vi = g_idx[1][row];
    float aadj = g_adj[0][row], vadj = g_adj[1][row];
    float tv = a[(size_t)row * DK + t] + v[(size_t)row * DK + t];
    atomicAdd(&g_wsum[0][vi][t], vadj * tv);   // video-driven pass
    atomicAdd(&g_wsum[1][ai][t], aadj * tv);   // audio-driven pass
    if (t == 0) {
        atomicAdd(&g_cnt[0][vi], vadj);
        atomicAdd(&g_cnt[1][ai], aadj);
    }
}

// -------- sequential EMA count normalization (1 block, M threads) --------
__global__ void k_ec(const float* __restrict__ ema_count) {
    __shared__ float sb[MC];
    int t = threadIdx.x;
    float ec = DECAYC * ema_count[t] + (1.f - DECAYC) * g_cnt[0][t];
    sb[t] = ec; __syncthreads();
    for (int o = 512; o > 0; o >>= 1) { if (t < o) sb[t] += sb[t + o]; __syncthreads(); }
    float n1 = sb[0]; __syncthreads();
    ec = (ec + EPSC) / (n1 + MC * EPSC) * n1;
    ec = DECAYC * ec + (1.f - DECAYC) * g_cnt[1][t];
    sb[t] = ec; __syncthreads();
    for (int o = 512; o > 0; o >>= 1) { if (t < o) sb[t] += sb[t + o]; __syncthreads(); }
    float n2 = sb[0]; __syncthreads();
    g_ec[t] = (ec + EPSC) / (n2 + MC * EPSC) * n2;
}

// -------- build normalized new codebook g_en --------
__global__ void k_en(const float* __restrict__ ema_weight) {
    __shared__ float sb[256];
    int m = blockIdx.x, t = threadIdx.x;
    float ew = (DECAYC * DECAYC) * ema_weight[(size_t)m * DK + t]
             + DECAYC * 0.5f * (1.f - DECAYC) * g_wsum[0][m][t]
             + 0.5f * (1.f - DECAYC) * g_wsum[1][m][t];
    float emb = ew / g_ec[m];
    sb[t] = emb * emb; __syncthreads();
    for (int o = 128; o > 0; o >>= 1) { if (t < o) sb[t] += sb[t + o]; __syncthreads(); }
    float nrm = sqrtf(sb[0]);
    g_en[m][t] = emb / fmaxf(nrm, 1e-8f);
}

// -------- phase-2 row pass: logsumexp + picked logits -> loss --------
__global__ void k_row2() {
    __shared__ float sred[256];
    __shared__ float spick[2];
    int row = blockIdx.x, z = blockIdx.y, t = threadIdx.x;
    const float* Srow = &g_S[z][row][0];
    float xs = g_xsq[z][row];
    float scale = 1.f / (fmaxf(sqrtf(xs), 1e-8f) * TEMPC);
    int self  = g_idx[z][row];
    int cross = g_idx[1 - z][row];

    float l[4], mx = -1e30f;
#pragma unroll
    for (int q = 0; q < 4; q++) {
        int m = q * 256 + t;
        l[q] = Srow[m] * scale;
        mx = fmaxf(mx, l[q]);
        if (m == self)  spick[0] = l[q];
        if (m == cross) spick[1] = l[q];
    }
    sred[t] = mx; __syncthreads();
    for (int o = 128; o > 0; o >>= 1) { if (t < o) sred[t] = fmaxf(sred[t], sred[t + o]); __syncthreads(); }
    float rmax = sred[0]; __syncthreads();
    float es = 0.f;
#pragma unroll
    for (int q = 0; q < 4; q++) es += __expf(l[q] - rmax);
    sred[t] = es; __syncthreads();
    for (int o = 128; o > 0; o >>= 1) { if (t < o) sred[t] += sred[t + o]; __syncthreads(); }
    if (t == 0) {
        float lse = __logf(sred[0]) + rmax;
        float contrib = lse - COMMITC * spick[0] - (1.f - COMMITC) * spick[1];
        atomicAdd(&g_loss, contrib);
    }
}

__global__ void k_final(float* __restrict__ out) {
    out[0] = COMMITC * g_loss / ((float)NTOK * (float)BV);
}

extern "C" void kernel_launch(void* const* d_in, const int* in_sizes, int n_in,
                              void* d_out, int out_size) {
    const float* audio      = (const float*)d_in[0];
    const float* video      = (const float*)d_in[1];
    const float* emb        = (const float*)d_in[2];
    const float* ema_count  = (const float*)d_in[3];
    const float* ema_weight = (const float*)d_in[4];
    float* out = (float*)d_out;

    k_zero<<<2048, 256>>>();
    k_sq<<<MC + 2 * NTOK, 256>>>(audio, video, emb);

    dim3 gg(MC / 128, NTOK / 128, 2);
    k_gemm<<<gg, 256>>>(audio, video, emb, 0);          // dist dots vs old codebook
    k_row1<<<dim3(NTOK, 2), 256>>>();
    k_scatter<<<NTOK, 256>>>(audio, video);
    k_ec<<<1, MC>>>(ema_count);
    k_en<<<MC, 256>>>(ema_weight);
    k_gemm<<<gg, 256>>>(audio, video, emb, 1);          // logits dots vs new codebook
    k_row2<<<dim3(NTOK, 2), 256>>>();
    k_final<<<1, 1>>>(out);
}